// round 1
// baseline (speedup 1.0000x reference)
#include <cuda_runtime.h>
#include <math.h>

#define BATCH 64
#define TT    2048
#define ENC   512
#define UNITS 512
#define VOCAB 32
#define NT    4      // n-tiles in score kernel (512/128)
#define TCH   8      // t-chunks for context partial sums

// ---- device scratch (no allocations allowed) ----
__device__ float g_hidden[BATCH * UNITS];          // s_t_m @ W2 + b2
__device__ float g_scoreP[BATCH * NT * TT];        // partial scores per n-tile
__device__ float g_w[BATCH * TT];                  // softmax weights
__device__ float g_ctxP[BATCH * TCH * ENC];        // partial context per t-chunk

// =====================================================================
// K1: hidden[b,u] = sum_k s_t_m[b,k] * W2[k,u] + W2_b[u]
// =====================================================================
__global__ void hidden_kernel(const float* __restrict__ s_t_m,
                              const float* __restrict__ W2,
                              const float* __restrict__ W2b) {
    __shared__ float s[UNITS];
    int b = blockIdx.x, u = threadIdx.x;
    s[u] = s_t_m[b * UNITS + u];
    __syncthreads();
    float acc = W2b[u];
    #pragma unroll 8
    for (int k = 0; k < UNITS; k++) acc += s[k] * W2[k * UNITS + u];
    g_hidden[b * UNITS + u] = acc;
}

// =====================================================================
// K2: fused score GEMM:  scoreP[b,ntile,t] = sum_{n in tile} V[n] *
//         tanh( (H[b,t,:] @ W1[:,n]) + W1_b[n] + hidden[b,n] )
// 128x128 block tile, BK=8, 256 threads, 8x8 register micro-tile.
// =====================================================================
__global__ void __launch_bounds__(256)
score_kernel(const float* __restrict__ H, const float* __restrict__ W1,
             const float* __restrict__ W1b, const float* __restrict__ Vw) {
    const int BM = 128, BN = 128, BK = 8;
    __shared__ float As[BK][BM];
    __shared__ float Bs[BK][BN];

    int b  = blockIdx.z;
    int n0 = blockIdx.y * BN;
    int t0 = blockIdx.x * BM;
    int tid = threadIdx.x;
    int tx = tid & 15, ty = tid >> 4;

    const float* A  = H  + (size_t)b * TT * ENC + (size_t)t0 * ENC;
    const float* Bp = W1 + n0;

    float acc[8][8];
    #pragma unroll
    for (int i = 0; i < 8; i++)
        #pragma unroll
        for (int j = 0; j < 8; j++) acc[i][j] = 0.f;

    // A-tile: 128 rows x 8 k -> 256 float4 loads (one per thread)
    int aRow = tid >> 1;
    int aK   = (tid & 1) * 4;
    // B-tile: 8 rows x 128 n -> 256 float4 loads
    int bRow = tid >> 5;
    int bCol = (tid & 31) * 4;

    for (int k0 = 0; k0 < ENC; k0 += BK) {
        float4 av = *(const float4*)(A + (size_t)aRow * ENC + k0 + aK);
        As[aK + 0][aRow] = av.x;
        As[aK + 1][aRow] = av.y;
        As[aK + 2][aRow] = av.z;
        As[aK + 3][aRow] = av.w;
        float4 bv = *(const float4*)(Bp + (size_t)(k0 + bRow) * UNITS + bCol);
        *(float4*)&Bs[bRow][bCol] = bv;
        __syncthreads();

        #pragma unroll
        for (int k = 0; k < BK; k++) {
            float4 a0 = *(const float4*)&As[k][ty * 8];
            float4 a1 = *(const float4*)&As[k][ty * 8 + 4];
            float4 b0 = *(const float4*)&Bs[k][tx * 8];
            float4 b1 = *(const float4*)&Bs[k][tx * 8 + 4];
            float ra[8] = {a0.x, a0.y, a0.z, a0.w, a1.x, a1.y, a1.z, a1.w};
            float rb[8] = {b0.x, b0.y, b0.z, b0.w, b1.x, b1.y, b1.z, b1.w};
            #pragma unroll
            for (int m = 0; m < 8; m++)
                #pragma unroll
                for (int n = 0; n < 8; n++)
                    acc[m][n] += ra[m] * rb[n];
        }
        __syncthreads();
    }

    // epilogue: bias + hidden, tanh, dot with V, reduce across tx (16 lanes)
    #pragma unroll
    for (int m = 0; m < 8; m++) {
        float p = 0.f;
        #pragma unroll
        for (int n = 0; n < 8; n++) {
            int nn = n0 + tx * 8 + n;
            float c = acc[m][n] + W1b[nn] + g_hidden[b * UNITS + nn];
            p += Vw[nn] * tanhf(c);
        }
        p += __shfl_xor_sync(0xffffffffu, p, 1);
        p += __shfl_xor_sync(0xffffffffu, p, 2);
        p += __shfl_xor_sync(0xffffffffu, p, 4);
        p += __shfl_xor_sync(0xffffffffu, p, 8);
        if (tx == 0)
            g_scoreP[((size_t)b * NT + blockIdx.y) * TT + t0 + ty * 8 + m] = p;
    }
}

// =====================================================================
// K3: softmax over T per batch.  (V_b is constant over t -> cancels.)
// =====================================================================
__global__ void softmax_kernel() {
    int b = blockIdx.x, tid = threadIdx.x;   // 256 threads, 8 t's each
    __shared__ float red[256];
    float sv[8];
    float mx = -1e30f;
    #pragma unroll
    for (int i = 0; i < 8; i++) {
        int t = tid + i * 256;
        float s = 0.f;
        #pragma unroll
        for (int p = 0; p < NT; p++) s += g_scoreP[((size_t)b * NT + p) * TT + t];
        sv[i] = s;
        mx = fmaxf(mx, s);
    }
    red[tid] = mx; __syncthreads();
    for (int o = 128; o > 0; o >>= 1) {
        if (tid < o) red[tid] = fmaxf(red[tid], red[tid + o]);
        __syncthreads();
    }
    mx = red[0]; __syncthreads();

    float sum = 0.f;
    #pragma unroll
    for (int i = 0; i < 8; i++) { sv[i] = expf(sv[i] - mx); sum += sv[i]; }
    red[tid] = sum; __syncthreads();
    for (int o = 128; o > 0; o >>= 1) {
        if (tid < o) red[tid] += red[tid + o];
        __syncthreads();
    }
    float inv = 1.f / red[0];
    #pragma unroll
    for (int i = 0; i < 8; i++) g_w[b * TT + tid + i * 256] = sv[i] * inv;
}

// =====================================================================
// K4: context partials: ctxP[b,ch,e] = sum_{t in chunk} w[b,t]*H[b,t,e]
// =====================================================================
__global__ void context_kernel(const float* __restrict__ H) {
    int b = blockIdx.y, ch = blockIdx.x, e = threadIdx.x;   // 512 threads
    const int TC = TT / TCH;                                // 256
    __shared__ float ws[TC];
    int tBeg = ch * TC;
    for (int i = threadIdx.x; i < TC; i += blockDim.x) ws[i] = g_w[b * TT + tBeg + i];
    __syncthreads();
    float acc = 0.f;
    const float* Hb = H + (size_t)b * TT * ENC + (size_t)tBeg * ENC + e;
    #pragma unroll 4
    for (int t = 0; t < TC; t++) acc += ws[t] * Hb[(size_t)t * ENC];
    g_ctxP[((size_t)b * TCH + ch) * ENC + e] = acc;
}

// =====================================================================
// K5: GRU step (Keras reset_after=True, gate order z,r,h)
// =====================================================================
__global__ void gru_kernel(const float* __restrict__ h_t, const float* __restrict__ s0,
                           const float* __restrict__ Wx, const float* __restrict__ Wh,
                           const float* __restrict__ bi, const float* __restrict__ br,
                           float* __restrict__ s_out) {
    __shared__ float xs[ENC], hs[UNITS];
    int b = blockIdx.x, u = threadIdx.x;
    xs[u] = h_t[b * ENC + u];
    hs[u] = s0[b * UNITS + u];
    __syncthreads();
    float xz = bi[u], xr = bi[UNITS + u], xh = bi[2 * UNITS + u];
    float hz = br[u], hr = br[UNITS + u], hh = br[2 * UNITS + u];
    #pragma unroll 4
    for (int k = 0; k < ENC; k++) {
        float x = xs[k];
        const float* w = Wx + (size_t)k * 3 * UNITS;
        xz += x * w[u];
        xr += x * w[UNITS + u];
        xh += x * w[2 * UNITS + u];
    }
    #pragma unroll 4
    for (int k = 0; k < UNITS; k++) {
        float h = hs[k];
        const float* w = Wh + (size_t)k * 3 * UNITS;
        hz += h * w[u];
        hr += h * w[UNITS + u];
        hh += h * w[2 * UNITS + u];
    }
    float z  = 1.f / (1.f + expf(-(xz + hz)));
    float r  = 1.f / (1.f + expf(-(xr + hr)));
    float hc = tanhf(xh + r * hh);
    s_out[b * UNITS + u] = z * hs[u] + (1.f - z) * hc;
}

// =====================================================================
// K6: gated fusion + vocab projection
// =====================================================================
__global__ void fusion_kernel(const float* __restrict__ Wfa, const float* __restrict__ Wfab,
                              const float* __restrict__ Wff, const float* __restrict__ Wffb,
                              const float* __restrict__ Wfh, const float* __restrict__ Wfhb,
                              const float* __restrict__ Wy,  const float* __restrict__ Wyb,
                              const float* __restrict__ s_t, float* __restrict__ y_out) {
    __shared__ float ctx[ENC], pc[UNITS], st[UNITS], ft[UNITS], yred[512];
    int b = blockIdx.x, u = threadIdx.x;

    float c = 0.f;
    #pragma unroll
    for (int ch = 0; ch < TCH; ch++) c += g_ctxP[((size_t)b * TCH + ch) * ENC + u];
    ctx[u] = c;
    st[u]  = s_t[b * UNITS + u];
    __syncthreads();

    float p = Wfab[u];
    #pragma unroll 4
    for (int k = 0; k < ENC; k++) p += ctx[k] * Wfa[(size_t)k * UNITS + u];
    pc[u] = p;
    __syncthreads();

    float fw = Wffb[u] + Wfhb[u];
    #pragma unroll 4
    for (int k = 0; k < UNITS; k++)
        fw += pc[k] * Wff[(size_t)k * UNITS + u] + st[k] * Wfh[(size_t)k * UNITS + u];
    fw = 1.f / (1.f + expf(-fw));
    ft[u] = pc[u] * fw + st[u];
    __syncthreads();

    // y: 32 vocab x 16 partial lanes
    int v = u & 31, part = u >> 5;
    float acc = 0.f;
    for (int k = part; k < UNITS; k += 16) acc += ft[k] * Wy[(size_t)k * VOCAB + v];
    yred[u] = acc;
    __syncthreads();
    if (part == 0) {
        float s = Wyb[v];
        #pragma unroll
        for (int pp = 0; pp < 16; pp++) s += yred[pp * 32 + v];
        y_out[b * VOCAB + v] = s;
    }
}

// =====================================================================
extern "C" void kernel_launch(void* const* d_in, const int* in_sizes, int n_in,
                              void* d_out, int out_size) {
    const float* h_t   = (const float*)d_in[0];
    const float* s_t_m = (const float*)d_in[1];
    const float* H     = (const float*)d_in[2];
    const float* s0    = (const float*)d_in[3];
    const float* W1w   = (const float*)d_in[4];
    const float* W1b   = (const float*)d_in[5];
    const float* W2w   = (const float*)d_in[6];
    const float* W2b   = (const float*)d_in[7];
    const float* Vw    = (const float*)d_in[8];
    // d_in[9] = V_b: additive constant over t, cancels in softmax (it is 0 anyway)
    const float* gWx   = (const float*)d_in[10];
    const float* gWh   = (const float*)d_in[11];
    const float* gbi   = (const float*)d_in[12];
    const float* gbr   = (const float*)d_in[13];
    const float* Wfa   = (const float*)d_in[14];
    const float* Wfab  = (const float*)d_in[15];
    const float* Wff   = (const float*)d_in[16];
    const float* Wffb  = (const float*)d_in[17];
    const float* Wfh   = (const float*)d_in[18];
    const float* Wfhb  = (const float*)d_in[19];
    const float* Wy    = (const float*)d_in[20];
    const float* Wyb   = (const float*)d_in[21];

    float* out   = (float*)d_out;
    float* y_out = out;                       // y_t: [64, 32]
    float* s_out = out + BATCH * VOCAB;       // s_t: [64, 512]

    hidden_kernel<<<BATCH, UNITS>>>(s_t_m, W2w, W2b);
    score_kernel<<<dim3(TT / 128, NT, BATCH), 256>>>(H, W1w, W1b, Vw);
    gru_kernel<<<BATCH, UNITS>>>(h_t, s0, gWx, gWh, gbi, gbr, s_out);
    softmax_kernel<<<BATCH, 256>>>();
    context_kernel<<<dim3(TCH, BATCH), 512>>>(H);
    fusion_kernel<<<BATCH, UNITS>>>(Wfa, Wfab, Wff, Wffb, Wfh, Wfhb, Wy, Wyb,
                                    s_out, y_out);
}

// round 2
// speedup vs baseline: 2.2403x; 2.2403x over previous
#include <cuda_runtime.h>
#include <math.h>
#include <stdint.h>

#define BATCH 64
#define TT    2048
#define ENC   512
#define UNITS 512
#define VOCAB 32
#define NT    4      // n-tiles in score kernel (512/128)
#define TCH   8      // t-chunks for context partial sums

// ---- device scratch (no allocations allowed) ----
__device__ float g_hidden[BATCH * UNITS];          // s_t_m @ W2 + b2
__device__ float g_scoreP[BATCH * NT * TT];        // partial scores per n-tile
__device__ float g_w[BATCH * TT];                  // softmax weights
__device__ float g_ctxP[BATCH * TCH * ENC];        // partial context per t-chunk

// =====================================================================
// K1: hidden[b,u] = sum_k s_t_m[b,k] * W2[k,u] + W2_b[u]
// =====================================================================
__global__ void hidden_kernel(const float* __restrict__ s_t_m,
                              const float* __restrict__ W2,
                              const float* __restrict__ W2b) {
    __shared__ float s[UNITS];
    int b = blockIdx.x, u = threadIdx.x;
    s[u] = s_t_m[b * UNITS + u];
    __syncthreads();
    float acc = W2b[u];
    #pragma unroll 8
    for (int k = 0; k < UNITS; k++) acc += s[k] * W2[k * UNITS + u];
    g_hidden[b * UNITS + u] = acc;
}

// =====================================================================
// K2: TF32 tensor-core score GEMM with fused tanh/V epilogue.
//   scoreP[b,ny,t] = sum_{n in tile} V[n] *
//       tanh( (H[b,t,:] @ W1[:,n]) + W1_b[n] + hidden[b,n] )
// Block 128(T) x 128(N) x K16, 256 thr, warp tile 64x32 (m16n8k8 tf32).
// cp.async double-buffered smem. As stride 20, Bs stride 136:
// both fragment-load patterns are 32-bank conflict-free.
// =====================================================================
#define CP16(dst, src) asm volatile( \
    "cp.async.cg.shared.global [%0], [%1], 16;\n" :: "r"(dst), "l"(src))
#define CP_COMMIT() asm volatile("cp.async.commit_group;\n")
#define CP_WAIT(N)  asm volatile("cp.async.wait_group %0;\n" :: "n"(N))

__device__ __forceinline__ void mma_tf32(float* c, const uint32_t* a, const uint32_t* b) {
    asm volatile(
        "mma.sync.aligned.m16n8k8.row.col.f32.tf32.tf32.f32 "
        "{%0,%1,%2,%3}, {%4,%5,%6,%7}, {%8,%9}, {%0,%1,%2,%3};\n"
        : "+f"(c[0]), "+f"(c[1]), "+f"(c[2]), "+f"(c[3])
        : "r"(a[0]), "r"(a[1]), "r"(a[2]), "r"(a[3]), "r"(b[0]), "r"(b[1]));
}

#define AS_STRIDE 20
#define BS_STRIDE 136

__global__ void __launch_bounds__(256, 2)
score_kernel(const float* __restrict__ H, const float* __restrict__ W1,
             const float* __restrict__ W1b, const float* __restrict__ Vw) {
    __shared__ __align__(16) float As[2][128][AS_STRIDE];   // [m][k]
    __shared__ __align__(16) float Bs[2][16][BS_STRIDE];    // [k][n]

    const int b  = blockIdx.z;
    const int n0 = blockIdx.y * 128;
    const int t0 = blockIdx.x * 128;
    const int tid = threadIdx.x;
    const int warpId = tid >> 5, lane = tid & 31;
    const int g = lane >> 2, tig = lane & 3;
    const int warpM = warpId & 1, warpN = warpId >> 1;
    const int mBase = warpM * 64, nBase = warpN * 32;

    const float* Ag = H  + (size_t)b * TT * ENC + (size_t)t0 * ENC;
    const float* Bg = W1 + n0;

    // A: 128x16 tile = 512 float4; thread handles idx tid, tid+256
    const int aRow0 = tid >> 2, aKc = (tid & 3) * 4, aRow1 = aRow0 + 64;
    // B: 16x128 tile = 512 float4; thread handles k rows tid>>5 and +8
    const int bK0 = tid >> 5, bN = (tid & 31) * 4, bK1 = bK0 + 8;

    uint32_t dA0[2], dA1[2], dB0[2], dB1[2];
    #pragma unroll
    for (int buf = 0; buf < 2; buf++) {
        dA0[buf] = (uint32_t)__cvta_generic_to_shared(&As[buf][aRow0][aKc]);
        dA1[buf] = (uint32_t)__cvta_generic_to_shared(&As[buf][aRow1][aKc]);
        dB0[buf] = (uint32_t)__cvta_generic_to_shared(&Bs[buf][bK0][bN]);
        dB1[buf] = (uint32_t)__cvta_generic_to_shared(&Bs[buf][bK1][bN]);
    }

    float acc[4][4][4];
    #pragma unroll
    for (int mt = 0; mt < 4; mt++)
        #pragma unroll
        for (int nt = 0; nt < 4; nt++)
            #pragma unroll
            for (int r = 0; r < 4; r++) acc[mt][nt][r] = 0.f;

    // prologue: stage 0
    CP16(dA0[0], Ag + (size_t)aRow0 * ENC + aKc);
    CP16(dA1[0], Ag + (size_t)aRow1 * ENC + aKc);
    CP16(dB0[0], Bg + (size_t)bK0 * UNITS + bN);
    CP16(dB1[0], Bg + (size_t)bK1 * UNITS + bN);
    CP_COMMIT();

    const int NS = ENC / 16;   // 32 stages
    for (int s = 0; s < NS; s++) {
        if (s < NS - 1) {
            int k0 = (s + 1) * 16;
            int nb = (s + 1) & 1;
            CP16(dA0[nb], Ag + (size_t)aRow0 * ENC + k0 + aKc);
            CP16(dA1[nb], Ag + (size_t)aRow1 * ENC + k0 + aKc);
            CP16(dB0[nb], Bg + (size_t)(k0 + bK0) * UNITS + bN);
            CP16(dB1[nb], Bg + (size_t)(k0 + bK1) * UNITS + bN);
            CP_COMMIT();
            CP_WAIT(1);
        } else {
            CP_WAIT(0);
        }
        __syncthreads();

        const int cur = s & 1;
        #pragma unroll
        for (int ks = 0; ks < 2; ks++) {
            const int kk = ks * 8;
            uint32_t af[4][4], bf[4][2];
            #pragma unroll
            for (int mt = 0; mt < 4; mt++) {
                int r = mBase + mt * 16 + g;
                af[mt][0] = __float_as_uint(As[cur][r    ][kk + tig]);
                af[mt][1] = __float_as_uint(As[cur][r + 8][kk + tig]);
                af[mt][2] = __float_as_uint(As[cur][r    ][kk + tig + 4]);
                af[mt][3] = __float_as_uint(As[cur][r + 8][kk + tig + 4]);
            }
            #pragma unroll
            for (int nt = 0; nt < 4; nt++) {
                int c = nBase + nt * 8 + g;
                bf[nt][0] = __float_as_uint(Bs[cur][kk + tig    ][c]);
                bf[nt][1] = __float_as_uint(Bs[cur][kk + tig + 4][c]);
            }
            #pragma unroll
            for (int mt = 0; mt < 4; mt++)
                #pragma unroll
                for (int nt = 0; nt < 4; nt++)
                    mma_tf32(acc[mt][nt], af[mt], bf[nt]);
        }
        __syncthreads();
    }

    // ---- epilogue: bias + hidden, tanh, dot V, reduce over n ----
    float pa[4], pb[4];
    #pragma unroll
    for (int mt = 0; mt < 4; mt++) { pa[mt] = 0.f; pb[mt] = 0.f; }

    #pragma unroll
    for (int nt = 0; nt < 4; nt++) {
        int c0 = n0 + nBase + nt * 8 + 2 * tig;
        float w0 = W1b[c0],     w1 = W1b[c0 + 1];
        float h0 = g_hidden[b * UNITS + c0], h1 = g_hidden[b * UNITS + c0 + 1];
        float v0 = Vw[c0],      v1 = Vw[c0 + 1];
        float s0 = w0 + h0, s1 = w1 + h1;
        #pragma unroll
        for (int mt = 0; mt < 4; mt++) {
            pa[mt] += v0 * tanhf(acc[mt][nt][0] + s0) + v1 * tanhf(acc[mt][nt][1] + s1);
            pb[mt] += v0 * tanhf(acc[mt][nt][2] + s0) + v1 * tanhf(acc[mt][nt][3] + s1);
        }
    }
    #pragma unroll
    for (int mt = 0; mt < 4; mt++) {
        pa[mt] += __shfl_xor_sync(0xffffffffu, pa[mt], 1);
        pa[mt] += __shfl_xor_sync(0xffffffffu, pa[mt], 2);
        pb[mt] += __shfl_xor_sync(0xffffffffu, pb[mt], 1);
        pb[mt] += __shfl_xor_sync(0xffffffffu, pb[mt], 2);
    }

    float* red = &As[0][0][0];   // 4 x 128 floats (safe after trailing sync)
    if (tig == 0) {
        #pragma unroll
        for (int mt = 0; mt < 4; mt++) {
            int r = mBase + mt * 16 + g;
            red[warpN * 128 + r]     = pa[mt];
            red[warpN * 128 + r + 8] = pb[mt];
        }
    }
    __syncthreads();
    if (tid < 128) {
        float s = red[tid] + red[128 + tid] + red[256 + tid] + red[384 + tid];
        g_scoreP[((size_t)b * NT + blockIdx.y) * TT + t0 + tid] = s;
    }
}

// =====================================================================
// K3: softmax over T per batch.  (V_b is constant over t -> cancels.)
// =====================================================================
__global__ void softmax_kernel() {
    int b = blockIdx.x, tid = threadIdx.x;   // 256 threads, 8 t's each
    __shared__ float red[256];
    float sv[8];
    float mx = -1e30f;
    #pragma unroll
    for (int i = 0; i < 8; i++) {
        int t = tid + i * 256;
        float s = 0.f;
        #pragma unroll
        for (int p = 0; p < NT; p++) s += g_scoreP[((size_t)b * NT + p) * TT + t];
        sv[i] = s;
        mx = fmaxf(mx, s);
    }
    red[tid] = mx; __syncthreads();
    for (int o = 128; o > 0; o >>= 1) {
        if (tid < o) red[tid] = fmaxf(red[tid], red[tid + o]);
        __syncthreads();
    }
    mx = red[0]; __syncthreads();

    float sum = 0.f;
    #pragma unroll
    for (int i = 0; i < 8; i++) { sv[i] = expf(sv[i] - mx); sum += sv[i]; }
    red[tid] = sum; __syncthreads();
    for (int o = 128; o > 0; o >>= 1) {
        if (tid < o) red[tid] += red[tid + o];
        __syncthreads();
    }
    float inv = 1.f / red[0];
    #pragma unroll
    for (int i = 0; i < 8; i++) g_w[b * TT + tid + i * 256] = sv[i] * inv;
}

// =====================================================================
// K4: context partials: ctxP[b,ch,e] = sum_{t in chunk} w[b,t]*H[b,t,e]
// =====================================================================
__global__ void context_kernel(const float* __restrict__ H) {
    int b = blockIdx.y, ch = blockIdx.x, e = threadIdx.x;   // 512 threads
    const int TC = TT / TCH;                                // 256
    __shared__ float ws[TC];
    int tBeg = ch * TC;
    for (int i = threadIdx.x; i < TC; i += blockDim.x) ws[i] = g_w[b * TT + tBeg + i];
    __syncthreads();
    float acc = 0.f;
    const float* Hb = H + (size_t)b * TT * ENC + (size_t)tBeg * ENC + e;
    #pragma unroll 4
    for (int t = 0; t < TC; t++) acc += ws[t] * Hb[(size_t)t * ENC];
    g_ctxP[((size_t)b * TCH + ch) * ENC + e] = acc;
}

// =====================================================================
// K5: GRU step (Keras reset_after=True, gate order z,r,h)
// =====================================================================
__global__ void gru_kernel(const float* __restrict__ h_t, const float* __restrict__ s0,
                           const float* __restrict__ Wx, const float* __restrict__ Wh,
                           const float* __restrict__ bi, const float* __restrict__ br,
                           float* __restrict__ s_out) {
    __shared__ float xs[ENC], hs[UNITS];
    int b = blockIdx.x, u = threadIdx.x;
    xs[u] = h_t[b * ENC + u];
    hs[u] = s0[b * UNITS + u];
    __syncthreads();
    float xz = bi[u], xr = bi[UNITS + u], xh = bi[2 * UNITS + u];
    float hz = br[u], hr = br[UNITS + u], hh = br[2 * UNITS + u];
    #pragma unroll 4
    for (int k = 0; k < ENC; k++) {
        float x = xs[k];
        const float* w = Wx + (size_t)k * 3 * UNITS;
        xz += x * w[u];
        xr += x * w[UNITS + u];
        xh += x * w[2 * UNITS + u];
    }
    #pragma unroll 4
    for (int k = 0; k < UNITS; k++) {
        float h = hs[k];
        const float* w = Wh + (size_t)k * 3 * UNITS;
        hz += h * w[u];
        hr += h * w[UNITS + u];
        hh += h * w[2 * UNITS + u];
    }
    float z  = 1.f / (1.f + expf(-(xz + hz)));
    float r  = 1.f / (1.f + expf(-(xr + hr)));
    float hc = tanhf(xh + r * hh);
    s_out[b * UNITS + u] = z * hs[u] + (1.f - z) * hc;
}

// =====================================================================
// K6: gated fusion + vocab projection
// =====================================================================
__global__ void fusion_kernel(const float* __restrict__ Wfa, const float* __restrict__ Wfab,
                              const float* __restrict__ Wff, const float* __restrict__ Wffb,
                              const float* __restrict__ Wfh, const float* __restrict__ Wfhb,
                              const float* __restrict__ Wy,  const float* __restrict__ Wyb,
                              const float* __restrict__ s_t, float* __restrict__ y_out) {
    __shared__ float ctx[ENC], pc[UNITS], st[UNITS], ft[UNITS], yred[512];
    int b = blockIdx.x, u = threadIdx.x;

    float c = 0.f;
    #pragma unroll
    for (int ch = 0; ch < TCH; ch++) c += g_ctxP[((size_t)b * TCH + ch) * ENC + u];
    ctx[u] = c;
    st[u]  = s_t[b * UNITS + u];
    __syncthreads();

    float p = Wfab[u];
    #pragma unroll 4
    for (int k = 0; k < ENC; k++) p += ctx[k] * Wfa[(size_t)k * UNITS + u];
    pc[u] = p;
    __syncthreads();

    float fw = Wffb[u] + Wfhb[u];
    #pragma unroll 4
    for (int k = 0; k < UNITS; k++)
        fw += pc[k] * Wff[(size_t)k * UNITS + u] + st[k] * Wfh[(size_t)k * UNITS + u];
    fw = 1.f / (1.f + expf(-fw));
    ft[u] = pc[u] * fw + st[u];
    __syncthreads();

    // y: 32 vocab x 16 partial lanes
    int v = u & 31, part = u >> 5;
    float acc = 0.f;
    for (int k = part; k < UNITS; k += 16) acc += ft[k] * Wy[(size_t)k * VOCAB + v];
    yred[u] = acc;
    __syncthreads();
    if (part == 0) {
        float s = Wyb[v];
        #pragma unroll
        for (int pp = 0; pp < 16; pp++) s += yred[pp * 32 + v];
        y_out[b * VOCAB + v] = s;
    }
}

// =====================================================================
extern "C" void kernel_launch(void* const* d_in, const int* in_sizes, int n_in,
                              void* d_out, int out_size) {
    const float* h_t   = (const float*)d_in[0];
    const float* s_t_m = (const float*)d_in[1];
    const float* H     = (const float*)d_in[2];
    const float* s0    = (const float*)d_in[3];
    const float* W1w   = (const float*)d_in[4];
    const float* W1b   = (const float*)d_in[5];
    const float* W2w   = (const float*)d_in[6];
    const float* W2b   = (const float*)d_in[7];
    const float* Vw    = (const float*)d_in[8];
    // d_in[9] = V_b: additive constant over t, cancels in softmax
    const float* gWx   = (const float*)d_in[10];
    const float* gWh   = (const float*)d_in[11];
    const float* gbi   = (const float*)d_in[12];
    const float* gbr   = (const float*)d_in[13];
    const float* Wfa   = (const float*)d_in[14];
    const float* Wfab  = (const float*)d_in[15];
    const float* Wff   = (const float*)d_in[16];
    const float* Wffb  = (const float*)d_in[17];
    const float* Wfh   = (const float*)d_in[18];
    const float* Wfhb  = (const float*)d_in[19];
    const float* Wy    = (const float*)d_in[20];
    const float* Wyb   = (const float*)d_in[21];

    float* out   = (float*)d_out;
    float* y_out = out;                       // y_t: [64, 32]
    float* s_out = out + BATCH * VOCAB;       // s_t: [64, 512]

    hidden_kernel<<<BATCH, UNITS>>>(s_t_m, W2w, W2b);
    score_kernel<<<dim3(TT / 128, NT, BATCH), 256>>>(H, W1w, W1b, Vw);
    gru_kernel<<<BATCH, UNITS>>>(h_t, s0, gWx, gWh, gbi, gbr, s_out);
    softmax_kernel<<<BATCH, 256>>>();
    context_kernel<<<dim3(TCH, BATCH), 512>>>(H);
    fusion_kernel<<<BATCH, UNITS>>>(Wfa, Wfab, Wff, Wffb, Wfh, Wfhb, Wy, Wyb,
                                    s_out, y_out);
}

// round 4
// speedup vs baseline: 3.3548x; 1.4975x over previous
#include <cuda_runtime.h>
#include <cuda_bf16.h>
#include <math.h>
#include <stdint.h>

#define BATCH 64
#define TT    2048
#define ENC   512
#define UNITS 512
#define VOCAB 32
#define TCH   8      // t-chunks for context partial sums

// ---- device scratch (no allocations allowed) ----
__device__ float g_hidden[BATCH * UNITS];                 // s_t_m @ W2 + b2
__device__ float g_scoreP[BATCH * 2 * TT];                // 2 n-partials of score
__device__ float g_w[BATCH * TT];                         // softmax weights
__device__ float g_ctxP[BATCH * TCH * ENC];               // partial context
__device__ float g_gateP[2 * 4 * BATCH * 3 * UNITS];      // gru gate k-partials
__device__ __align__(16) __nv_bfloat16 g_Hb[(size_t)BATCH * TT * ENC];  // H in bf16
__device__ __align__(16) __nv_bfloat16 g_W1Tb[UNITS * ENC];             // W1^T bf16 [n][k]

// =====================================================================
// helpers
// =====================================================================
__device__ __forceinline__ uint32_t smem_u32(const void* p) {
    uint32_t a;
    asm("{ .reg .u64 t; cvta.to.shared.u64 t, %1; cvt.u32.u64 %0, t; }"
        : "=r"(a) : "l"(p));
    return a;
}
#define CP16(dst, src) asm volatile( \
    "cp.async.cg.shared.global [%0], [%1], 16;\n" :: "r"(dst), "l"(src))
#define CP_COMMIT() asm volatile("cp.async.commit_group;\n")
#define CP_WAIT1()  asm volatile("cp.async.wait_group 1;\n")
#define CP_WAIT0()  asm volatile("cp.async.wait_group 0;\n")

__device__ __forceinline__ void mma_bf16(float* c, const uint32_t* a, const uint32_t* b) {
    asm volatile(
        "mma.sync.aligned.m16n8k16.row.col.f32.bf16.bf16.f32 "
        "{%0,%1,%2,%3}, {%4,%5,%6,%7}, {%8,%9}, {%0,%1,%2,%3};\n"
        : "+f"(c[0]), "+f"(c[1]), "+f"(c[2]), "+f"(c[3])
        : "r"(a[0]), "r"(a[1]), "r"(a[2]), "r"(a[3]), "r"(b[0]), "r"(b[1]));
}
__device__ __forceinline__ float tanh_fast(float x) {
    float r;
    asm("tanh.approx.f32 %0, %1;" : "=f"(r) : "f"(x));
    return r;
}

// =====================================================================
// K0a: convert H (fp32) -> g_Hb (bf16), 8 elems/thread
// =====================================================================
__global__ void convH_kernel(const float* __restrict__ H) {
    size_t i = ((size_t)blockIdx.x * 256 + threadIdx.x) * 8;
    float4 a = *(const float4*)(H + i);
    float4 b = *(const float4*)(H + i + 4);
    __nv_bfloat162 r0 = __floats2bfloat162_rn(a.x, a.y);
    __nv_bfloat162 r1 = __floats2bfloat162_rn(a.z, a.w);
    __nv_bfloat162 r2 = __floats2bfloat162_rn(b.x, b.y);
    __nv_bfloat162 r3 = __floats2bfloat162_rn(b.z, b.w);
    uint4 o;
    o.x = *(uint32_t*)&r0; o.y = *(uint32_t*)&r1;
    o.z = *(uint32_t*)&r2; o.w = *(uint32_t*)&r3;
    *(uint4*)(g_Hb + i) = o;
}

// K0b: W1 [k][n] fp32 -> g_W1Tb [n][k] bf16
__global__ void convW1_kernel(const float* __restrict__ W1) {
    __shared__ float t[32][33];
    int bx = blockIdx.x * 32, by = blockIdx.y * 32;
    t[threadIdx.y][threadIdx.x] = W1[(by + threadIdx.y) * UNITS + bx + threadIdx.x];
    __syncthreads();
    g_W1Tb[(size_t)(bx + threadIdx.y) * ENC + by + threadIdx.x] =
        __float2bfloat16(t[threadIdx.x][threadIdx.y]);
}

// =====================================================================
// K1: hidden[b,u] = s_t_m[b,:] @ W2[:,u] + W2_b[u]
// =====================================================================
__global__ void hidden_kernel(const float* __restrict__ s_t_m,
                              const float* __restrict__ W2,
                              const float* __restrict__ W2b) {
    __shared__ float s[UNITS];
    int b = blockIdx.x, u = threadIdx.x;
    s[u] = s_t_m[b * UNITS + u];
    __syncthreads();
    float acc = W2b[u];
    #pragma unroll 8
    for (int k = 0; k < UNITS; k++) acc += s[k] * W2[k * UNITS + u];
    g_hidden[b * UNITS + u] = acc;
}

// =====================================================================
// K2: bf16 mma.sync score GEMM, block 128(T) x 256(N), K staged by 32.
//   scoreP[b,ny,t] = sum_{n in half} V[n]*tanh(H@W1 + W1b[n] + hidden[b,n])
// Warp grid 2(M)x4(N), warp tile 64x64, m16n8k16.
// Smem u32 stride 20 -> all fragment LDS patterns 32-bank conflict-free.
// =====================================================================
#define AS_U32   2560u      // 128 rows * 20 u32 per buffer
#define BS_U32   5120u      // 256 rows * 20 u32 per buffer
#define SMEM_SCORE_BYTES 65536

__global__ void __launch_bounds__(256, 1)
score_kernel(const float* __restrict__ W1b, const float* __restrict__ Vw) {
    extern __shared__ uint32_t dyn[];
    float* sbias = (float*)(dyn + 15360);   // 256 f
    float* sV    = sbias + 256;             // 256 f
    float* red   = sV + 256;                // 512 f

    const int tid = threadIdx.x;
    const int w = tid >> 5, lane = tid & 31;
    const int g = lane >> 2, tig = lane & 3;
    const int warpM = w & 1, warpN = w >> 1;
    const int b = blockIdx.z, t0 = blockIdx.x * 128, n0 = blockIdx.y * 256;
    const uint32_t sbase = smem_u32(dyn);

    sbias[tid & 255] = W1b[n0 + (tid & 255)] + g_hidden[b * UNITS + n0 + (tid & 255)];
    sV[tid & 255]    = Vw[n0 + (tid & 255)];

    const __nv_bfloat16* Ag = g_Hb   + ((size_t)b * TT + t0) * ENC;
    const __nv_bfloat16* Bg = g_W1Tb + (size_t)n0 * ENC;

    auto load_chunk = [&](int buf, int k0) {
        #pragma unroll
        for (int j = 0; j < 2; j++) {               // A: 128 x 32 bf16
            int e = tid + j * 256, r = e >> 2, s = e & 3;
            CP16(sbase + ((uint32_t)buf * AS_U32 + r * 20 + s * 4) * 4,
                 Ag + (size_t)r * ENC + k0 + s * 8);
        }
        #pragma unroll
        for (int j = 0; j < 4; j++) {               // B: 256 x 32 bf16
            int e = tid + j * 256, r = e >> 2, s = e & 3;
            CP16(sbase + (2 * AS_U32 + (uint32_t)buf * BS_U32 + r * 20 + s * 4) * 4,
                 Bg + (size_t)r * ENC + k0 + s * 8);
        }
    };

    float acc[4][8][4];
    #pragma unroll
    for (int mt = 0; mt < 4; mt++)
        #pragma unroll
        for (int nt = 0; nt < 8; nt++)
            #pragma unroll
            for (int q = 0; q < 4; q++) acc[mt][nt][q] = 0.f;

    load_chunk(0, 0);
    CP_COMMIT();

    const int NS = ENC / 32;   // 16 stages
    for (int s = 0; s < NS; s++) {
        if (s < NS - 1) {
            load_chunk((s + 1) & 1, (s + 1) * 32);
            CP_COMMIT();
            CP_WAIT1();
        } else {
            CP_WAIT0();
        }
        __syncthreads();
        const uint32_t* Ab = dyn + (uint32_t)(s & 1) * AS_U32;
        const uint32_t* Bb = dyn + 2 * AS_U32 + (uint32_t)(s & 1) * BS_U32;

        #pragma unroll
        for (int kk = 0; kk < 2; kk++) {
            const int kw = kk * 8;
            uint32_t af[4][4], bf[8][2];
            #pragma unroll
            for (int mt = 0; mt < 4; mt++) {
                int r = warpM * 64 + mt * 16 + g;
                af[mt][0] = Ab[r * 20 + kw + tig];
                af[mt][1] = Ab[(r + 8) * 20 + kw + tig];
                af[mt][2] = Ab[r * 20 + kw + tig + 4];
                af[mt][3] = Ab[(r + 8) * 20 + kw + tig + 4];
            }
            #pragma unroll
            for (int nt = 0; nt < 8; nt++) {
                int c = warpN * 64 + nt * 8 + g;
                bf[nt][0] = Bb[c * 20 + kw + tig];
                bf[nt][1] = Bb[c * 20 + kw + tig + 4];
            }
            #pragma unroll
            for (int mt = 0; mt < 4; mt++)
                #pragma unroll
                for (int nt = 0; nt < 8; nt++)
                    mma_bf16(acc[mt][nt], af[mt], bf[nt]);
        }
        __syncthreads();
    }

    // epilogue: bias+hidden, tanh, dot V, reduce over n
    float pa[4], pb[4];
    #pragma unroll
    for (int mt = 0; mt < 4; mt++) { pa[mt] = 0.f; pb[mt] = 0.f; }
    #pragma unroll
    for (int nt = 0; nt < 8; nt++) {
        int nn = warpN * 64 + nt * 8 + 2 * tig;
        float s0 = sbias[nn], s1 = sbias[nn + 1];
        float v0 = sV[nn],    v1 = sV[nn + 1];
        #pragma unroll
        for (int mt = 0; mt < 4; mt++) {
            pa[mt] += v0 * tanh_fast(acc[mt][nt][0] + s0) + v1 * tanh_fast(acc[mt][nt][1] + s1);
            pb[mt] += v0 * tanh_fast(acc[mt][nt][2] + s0) + v1 * tanh_fast(acc[mt][nt][3] + s1);
        }
    }
    #pragma unroll
    for (int mt = 0; mt < 4; mt++) {
        pa[mt] += __shfl_xor_sync(0xffffffffu, pa[mt], 1);
        pa[mt] += __shfl_xor_sync(0xffffffffu, pa[mt], 2);
        pb[mt] += __shfl_xor_sync(0xffffffffu, pb[mt], 1);
        pb[mt] += __shfl_xor_sync(0xffffffffu, pb[mt], 2);
    }
    if (tig == 0) {
        #pragma unroll
        for (int mt = 0; mt < 4; mt++) {
            int r = warpM * 64 + mt * 16 + g;
            red[warpN * 128 + r]     = pa[mt];
            red[warpN * 128 + r + 8] = pb[mt];
        }
    }
    __syncthreads();
    if (tid < 128) {
        float s = red[tid] + red[128 + tid] + red[256 + tid] + red[384 + tid];
        g_scoreP[((size_t)b * 2 + blockIdx.y) * TT + t0 + tid] = s;
    }
}

// =====================================================================
// K3: softmax over T per batch (V_b constant -> cancels)
// =====================================================================
__global__ void softmax_kernel() {
    int b = blockIdx.x, tid = threadIdx.x;   // 256 threads, 8 t's each
    __shared__ float red[256];
    float sv[8];
    float mx = -1e30f;
    #pragma unroll
    for (int i = 0; i < 8; i++) {
        int t = tid + i * 256;
        sv[i] = g_scoreP[(size_t)b * 2 * TT + t] + g_scoreP[((size_t)b * 2 + 1) * TT + t];
        mx = fmaxf(mx, sv[i]);
    }
    red[tid] = mx; __syncthreads();
    for (int o = 128; o > 0; o >>= 1) {
        if (tid < o) red[tid] = fmaxf(red[tid], red[tid + o]);
        __syncthreads();
    }
    mx = red[0]; __syncthreads();
    float sum = 0.f;
    #pragma unroll
    for (int i = 0; i < 8; i++) { sv[i] = expf(sv[i] - mx); sum += sv[i]; }
    red[tid] = sum; __syncthreads();
    for (int o = 128; o > 0; o >>= 1) {
        if (tid < o) red[tid] += red[tid + o];
        __syncthreads();
    }
    float inv = 1.f / red[0];
    #pragma unroll
    for (int i = 0; i < 8; i++) g_w[b * TT + tid + i * 256] = sv[i] * inv;
}

// =====================================================================
// K4: context partials from bf16 H
// =====================================================================
__global__ void context_kernel() {
    int b = blockIdx.y, ch = blockIdx.x, e = threadIdx.x;   // 512 threads
    const int TC = TT / TCH;                                // 256
    __shared__ float ws[TC];
    int tBeg = ch * TC;
    for (int i = threadIdx.x; i < TC; i += blockDim.x) ws[i] = g_w[b * TT + tBeg + i];
    __syncthreads();
    float acc = 0.f;
    const __nv_bfloat16* Hb = g_Hb + (size_t)b * TT * ENC + (size_t)tBeg * ENC + e;
    #pragma unroll 4
    for (int t = 0; t < TC; t++) acc += ws[t] * __bfloat162float(Hb[(size_t)t * ENC]);
    g_ctxP[((size_t)b * TCH + ch) * ENC + e] = acc;
}

// =====================================================================
// K5a: GRU gate GEMM partials.
//  G[path][kz][b][c] = sum_{k in kz-slice} In[b][k] * W[k][c]
//  grid (12 c-tiles, 2 paths, 4 k-splits), block 256.
// =====================================================================
__global__ void gru_gates_kernel(const float* __restrict__ h_t,
                                 const float* __restrict__ s0,
                                 const float* __restrict__ Wx,
                                 const float* __restrict__ Wh) {
    const int path = blockIdx.y, kz = blockIdx.z;
    const float* In = path ? s0 : h_t;
    const float* W  = path ? Wh : Wx;
    const int c0 = blockIdx.x * 128;
    const int tid = threadIdx.x, tc = tid & 127, bh = tid >> 7;
    __shared__ float xs[64][8];
    __shared__ float Ws[8][128];
    float acc[32];
    #pragma unroll
    for (int i = 0; i < 32; i++) acc[i] = 0.f;

    const int kbeg = kz * 128;
    for (int k0 = kbeg; k0 < kbeg + 128; k0 += 8) {
        #pragma unroll
        for (int j = 0; j < 2; j++) {
            int e = tid + j * 256;
            xs[e >> 3][e & 7] = In[(e >> 3) * UNITS + k0 + (e & 7)];
        }
        #pragma unroll
        for (int j = 0; j < 4; j++) {
            int e = tid + j * 256;
            Ws[e >> 7][e & 127] = W[(size_t)(k0 + (e >> 7)) * (3 * UNITS) + c0 + (e & 127)];
        }
        __syncthreads();
        #pragma unroll
        for (int kk = 0; kk < 8; kk++) {
            float wv = Ws[kk][tc];
            #pragma unroll
            for (int bb = 0; bb < 32; bb++) acc[bb] += xs[bh * 32 + bb][kk] * wv;
        }
        __syncthreads();
    }
    #pragma unroll
    for (int bb = 0; bb < 32; bb++)
        g_gateP[((size_t)(path * 4 + kz) * BATCH + bh * 32 + bb) * (3 * UNITS) + c0 + tc] = acc[bb];
}

// K5b: combine gates -> s_t (Keras reset_after=True, gate order z,r,h)
__global__ void gru_combine_kernel(const float* __restrict__ s0,
                                   const float* __restrict__ bi,
                                   const float* __restrict__ br,
                                   float* __restrict__ s_out) {
    int b = blockIdx.x, u = threadIdx.x;
    float xz = bi[u], xr = bi[UNITS + u], xh = bi[2 * UNITS + u];
    float hz = br[u], hr = br[UNITS + u], hh = br[2 * UNITS + u];
    #pragma unroll
    for (int p = 0; p < 4; p++) {
        const float* X  = g_gateP + ((size_t)(0 * 4 + p) * BATCH + b) * (3 * UNITS);
        const float* Hg = g_gateP + ((size_t)(1 * 4 + p) * BATCH + b) * (3 * UNITS);
        xz += X[u];  xr += X[UNITS + u];  xh += X[2 * UNITS + u];
        hz += Hg[u]; hr += Hg[UNITS + u]; hh += Hg[2 * UNITS + u];
    }
    float hprev = s0[b * UNITS + u];
    float z  = 1.f / (1.f + expf(-(xz + hz)));
    float r  = 1.f / (1.f + expf(-(xr + hr)));
    float hc = tanhf(xh + r * hh);
    s_out[b * UNITS + u] = z * hprev + (1.f - z) * hc;
}

// =====================================================================
// K6: gated fusion + vocab projection
// =====================================================================
__global__ void fusion_kernel(const float* __restrict__ Wfa, const float* __restrict__ Wfab,
                              const float* __restrict__ Wff, const float* __restrict__ Wffb,
                              const float* __restrict__ Wfh, const float* __restrict__ Wfhb,
                              const float* __restrict__ Wy,  const float* __restrict__ Wyb,
                              const float* __restrict__ s_t, float* __restrict__ y_out) {
    __shared__ float ctx[ENC], pc[UNITS], st[UNITS], ft[UNITS], yred[512];
    int b = blockIdx.x, u = threadIdx.x;

    float c = 0.f;
    #pragma unroll
    for (int ch = 0; ch < TCH; ch++) c += g_ctxP[((size_t)b * TCH + ch) * ENC + u];
    ctx[u] = c;
    st[u]  = s_t[b * UNITS + u];
    __syncthreads();

    float p = Wfab[u];
    #pragma unroll 4
    for (int k = 0; k < ENC; k++) p += ctx[k] * Wfa[(size_t)k * UNITS + u];
    pc[u] = p;
    __syncthreads();

    float fw = Wffb[u] + Wfhb[u];
    #pragma unroll 4
    for (int k = 0; k < UNITS; k++)
        fw += pc[k] * Wff[(size_t)k * UNITS + u] + st[k] * Wfh[(size_t)k * UNITS + u];
    fw = 1.f / (1.f + expf(-fw));
    ft[u] = pc[u] * fw + st[u];
    __syncthreads();

    int v = u & 31, part = u >> 5;
    float acc = 0.f;
    for (int k = part; k < UNITS; k += 16) acc += ft[k] * Wy[(size_t)k * VOCAB + v];
    yred[u] = acc;
    __syncthreads();
    if (part == 0) {
        float s = Wyb[v];
        #pragma unroll
        for (int pp = 0; pp < 16; pp++) s += yred[pp * 32 + v];
        y_out[b * VOCAB + v] = s;
    }
}

// =====================================================================
extern "C" void kernel_launch(void* const* d_in, const int* in_sizes, int n_in,
                              void* d_out, int out_size) {
    const float* h_t   = (const float*)d_in[0];
    const float* s_t_m = (const float*)d_in[1];
    const float* H     = (const float*)d_in[2];
    const float* s0    = (const float*)d_in[3];
    const float* W1w   = (const float*)d_in[4];
    const float* W1b   = (const float*)d_in[5];
    const float* W2w   = (const float*)d_in[6];
    const float* W2b   = (const float*)d_in[7];
    const float* Vw    = (const float*)d_in[8];
    // d_in[9] = V_b: additive constant over t, cancels in softmax
    const float* gWx   = (const float*)d_in[10];
    const float* gWh   = (const float*)d_in[11];
    const float* gbi   = (const float*)d_in[12];
    const float* gbr   = (const float*)d_in[13];
    const float* Wfa   = (const float*)d_in[14];
    const float* Wfab  = (const float*)d_in[15];
    const float* Wff   = (const float*)d_in[16];
    const float* Wffb  = (const float*)d_in[17];
    const float* Wfh   = (const float*)d_in[18];
    const float* Wfhb  = (const float*)d_in[19];
    const float* Wy    = (const float*)d_in[20];
    const float* Wyb   = (const float*)d_in[21];

    float* out   = (float*)d_out;
    float* y_out = out;                       // y_t: [64, 32]
    float* s_out = out + BATCH * VOCAB;       // s_t: [64, 512]

    cudaFuncSetAttribute(score_kernel,
                         cudaFuncAttributeMaxDynamicSharedMemorySize, SMEM_SCORE_BYTES);

    convH_kernel<<<32768, 256>>>(H);
    convW1_kernel<<<dim3(16, 16), dim3(32, 32)>>>(W1w);
    hidden_kernel<<<BATCH, UNITS>>>(s_t_m, W2w, W2b);
    gru_gates_kernel<<<dim3(12, 2, 4), 256>>>(h_t, s0, gWx, gWh);
    score_kernel<<<dim3(TT / 128, 2, BATCH), 256, SMEM_SCORE_BYTES>>>(W1b, Vw);
    gru_combine_kernel<<<BATCH, UNITS>>>(s0, gbi, gbr, s_out);
    softmax_kernel<<<BATCH, 256>>>();
    context_kernel<<<dim3(TCH, BATCH), 512>>>();
    fusion_kernel<<<BATCH, UNITS>>>(Wfa, Wfab, Wff, Wffb, Wfh, Wfhb, Wy, Wyb,
                                    s_out, y_out);
}

// round 5
// speedup vs baseline: 4.0266x; 1.2003x over previous
#include <cuda_runtime.h>
#include <cuda_bf16.h>
#include <math.h>
#include <stdint.h>

#define BATCH 64
#define TT    2048
#define ENC   512
#define UNITS 512
#define VOCAB 32
#define TCH   8

// ---- device scratch (no allocations allowed) ----
__device__ float g_hidden[BATCH * UNITS];
__device__ float g_scoreP[BATCH * 2 * TT];
__device__ float g_w[BATCH * TT];
__device__ float g_ctxP[BATCH * TCH * ENC];
__device__ float g_gxP[8 * BATCH * 3 * UNITS];
__device__ float g_ghP[8 * BATCH * 3 * UNITS];
__device__ float g_hidP[8 * BATCH * UNITS];
__device__ __align__(16) __nv_bfloat16 g_Hb[(size_t)BATCH * TT * ENC];
__device__ __align__(16) __nv_bfloat16 g_W1Tb[UNITS * ENC];   // W1^T [n][k]

// =====================================================================
// helpers
// =====================================================================
__device__ __forceinline__ uint32_t smem_u32(const void* p) {
    uint32_t a;
    asm("{ .reg .u64 t; cvta.to.shared.u64 t, %1; cvt.u32.u64 %0, t; }"
        : "=r"(a) : "l"(p));
    return a;
}
#define CP16(dst, src) asm volatile( \
    "cp.async.cg.shared.global [%0], [%1], 16;\n" :: "r"(dst), "l"(src))
#define CP_COMMIT() asm volatile("cp.async.commit_group;\n")
#define CP_WAIT1()  asm volatile("cp.async.wait_group 1;\n")
#define CP_WAIT0()  asm volatile("cp.async.wait_group 0;\n")
#define LDSM4(R0, R1, R2, R3, A) asm volatile( \
    "ldmatrix.sync.aligned.m8n8.x4.shared.b16 {%0,%1,%2,%3}, [%4];" \
    : "=r"(R0), "=r"(R1), "=r"(R2), "=r"(R3) : "r"(A))

__device__ __forceinline__ void mma_bf16(float* c, const uint32_t* a, const uint32_t* b) {
    asm volatile(
        "mma.sync.aligned.m16n8k16.row.col.f32.bf16.bf16.f32 "
        "{%0,%1,%2,%3}, {%4,%5,%6,%7}, {%8,%9}, {%0,%1,%2,%3};\n"
        : "+f"(c[0]), "+f"(c[1]), "+f"(c[2]), "+f"(c[3])
        : "r"(a[0]), "r"(a[1]), "r"(a[2]), "r"(a[3]), "r"(b[0]), "r"(b[1]));
}
__device__ __forceinline__ float tanh_fast(float x) {
    float r;
    asm("tanh.approx.f32 %0, %1;" : "=f"(r) : "f"(x));
    return r;
}

// =====================================================================
// K0a: H fp32 -> bf16
// =====================================================================
__global__ void convH_kernel(const float* __restrict__ H) {
    size_t i = ((size_t)blockIdx.x * 256 + threadIdx.x) * 8;
    float4 a = *(const float4*)(H + i);
    float4 b = *(const float4*)(H + i + 4);
    __nv_bfloat162 r0 = __floats2bfloat162_rn(a.x, a.y);
    __nv_bfloat162 r1 = __floats2bfloat162_rn(a.z, a.w);
    __nv_bfloat162 r2 = __floats2bfloat162_rn(b.x, b.y);
    __nv_bfloat162 r3 = __floats2bfloat162_rn(b.z, b.w);
    uint4 o;
    o.x = *(uint32_t*)&r0; o.y = *(uint32_t*)&r1;
    o.z = *(uint32_t*)&r2; o.w = *(uint32_t*)&r3;
    *(uint4*)(g_Hb + i) = o;
}

// K0b: W1 [k][n] fp32 -> g_W1Tb [n][k] bf16
__global__ void convW1_kernel(const float* __restrict__ W1) {
    __shared__ float t[32][33];
    int bx = blockIdx.x * 32, by = blockIdx.y * 32;
    t[threadIdx.y][threadIdx.x] = W1[(by + threadIdx.y) * UNITS + bx + threadIdx.x];
    __syncthreads();
    g_W1Tb[(size_t)(bx + threadIdx.y) * ENC + by + threadIdx.x] =
        __float2bfloat16(t[threadIdx.x][threadIdx.y]);
}

// =====================================================================
// K1: batched small GEMM partial: outP[kz][b][c] = In[b, kz*64:+64] @ W[., c]
// grid (C/128, 8), block 256.  Used for GRU x/h paths and hidden proj.
// =====================================================================
__global__ void gemm64_kernel(const float* __restrict__ In,
                              const float* __restrict__ W, int ldW,
                              float* __restrict__ outP) {
    const int c0 = blockIdx.x * 128;
    const int kz = blockIdx.y;
    const int tid = threadIdx.x, tc = tid & 127, bh = tid >> 7;
    __shared__ float xs[64][8];
    __shared__ float Ws[8][128];
    float acc[32];
    #pragma unroll
    for (int i = 0; i < 32; i++) acc[i] = 0.f;

    const int kbeg = kz * 64;
    for (int k0 = kbeg; k0 < kbeg + 64; k0 += 8) {
        #pragma unroll
        for (int j = 0; j < 2; j++) {
            int e = tid + j * 256;
            xs[e >> 3][e & 7] = In[(e >> 3) * UNITS + k0 + (e & 7)];
        }
        #pragma unroll
        for (int j = 0; j < 4; j++) {
            int e = tid + j * 256;
            Ws[e >> 7][e & 127] = W[(size_t)(k0 + (e >> 7)) * ldW + c0 + (e & 127)];
        }
        __syncthreads();
        #pragma unroll
        for (int kk = 0; kk < 8; kk++) {
            float wv = Ws[kk][tc];
            #pragma unroll
            for (int bb = 0; bb < 32; bb++) acc[bb] += xs[bh * 32 + bb][kk] * wv;
        }
        __syncthreads();
    }
    #pragma unroll
    for (int bb = 0; bb < 32; bb++)
        outP[((size_t)kz * BATCH + bh * 32 + bb) * ldW + c0 + tc] = acc[bb];
}

__global__ void hidden_combine_kernel(const float* __restrict__ W2b) {
    int b = blockIdx.x, u = threadIdx.x;
    float a = W2b[u];
    #pragma unroll
    for (int p = 0; p < 8; p++) a += g_hidP[((size_t)p * BATCH + b) * UNITS + u];
    g_hidden[b * UNITS + u] = a;
}

// =====================================================================
// K2: bf16 mma.sync + ldmatrix score GEMM. Block 128(T) x 256(N), K chunk 64.
//   scoreP[b,ny,t] = sum_{n in half} V[n]*tanh(H@W1 + W1b[n] + hidden[b,n])
// SW128 swizzle on 128B rows; double-buffered cp.async.
// =====================================================================
#define SM_A(buf) ((uint32_t)(buf) * 16384u)
#define SM_B(buf) (32768u + (uint32_t)(buf) * 32768u)
#define SMEM_SCORE_BYTES 102400

__global__ void __launch_bounds__(256, 1)
score_kernel(const float* __restrict__ W1b, const float* __restrict__ Vw) {
    extern __shared__ uint32_t dyn[];
    float* sbias = (float*)(dyn + 24576);   // 256 f
    float* sV    = sbias + 256;             // 256 f
    float* red   = sV + 256;                // 512 f

    const int tid = threadIdx.x;
    const int w = tid >> 5, lane = tid & 31;
    const int g = lane >> 2, tig = lane & 3;
    const int warpM = w & 1, warpN = w >> 1;
    const int b = blockIdx.z, t0 = blockIdx.x * 128, n0 = blockIdx.y * 256;
    const uint32_t sbase = smem_u32(dyn);

    sbias[tid] = W1b[n0 + tid] + g_hidden[b * UNITS + n0 + tid];
    sV[tid]    = Vw[n0 + tid];

    const __nv_bfloat16* Ag = g_Hb   + ((size_t)b * TT + t0) * ENC;
    const __nv_bfloat16* Bg = g_W1Tb + (size_t)n0 * ENC;

    auto load_chunk = [&](int buf, int k0) {
        #pragma unroll
        for (int j = 0; j < 4; j++) {               // A: 128 rows x 8 segs
            int e = tid + j * 256, r = e >> 3, s = e & 7;
            uint32_t off = SM_A(buf) + (uint32_t)r * 128u
                         + (uint32_t)((s ^ (r & 7)) << 4);
            CP16(sbase + off, Ag + (size_t)r * ENC + k0 + s * 8);
        }
        #pragma unroll
        for (int j = 0; j < 8; j++) {               // B: 256 rows x 8 segs
            int e = tid + j * 256, r = e >> 3, s = e & 7;
            uint32_t off = SM_B(buf) + (uint32_t)r * 128u
                         + (uint32_t)((s ^ (r & 7)) << 4);
            CP16(sbase + off, Bg + (size_t)r * ENC + k0 + s * 8);
        }
    };

    // ldmatrix per-thread row offsets
    uint32_t aOff[4], aRs[4], bOff[4], bRs[4];
    const uint32_t aHi = (lane >> 4) & 1;
    const uint32_t bHi = (lane >> 3) & 1;
    #pragma unroll
    for (int mt = 0; mt < 4; mt++) {
        int row = warpM * 64 + mt * 16 + (lane & 15);
        aOff[mt] = (uint32_t)row * 128u;
        aRs[mt]  = (uint32_t)(row & 7);
    }
    #pragma unroll
    for (int pr = 0; pr < 4; pr++) {
        int n = warpN * 64 + pr * 16 + (lane & 7) + ((lane >> 4) << 3);
        bOff[pr] = (uint32_t)n * 128u;
        bRs[pr]  = (uint32_t)(n & 7);
    }

    float acc[4][8][4];
    #pragma unroll
    for (int mt = 0; mt < 4; mt++)
        #pragma unroll
        for (int nt = 0; nt < 8; nt++)
            #pragma unroll
            for (int q = 0; q < 4; q++) acc[mt][nt][q] = 0.f;

    load_chunk(0, 0);
    CP_COMMIT();

    const int NS = ENC / 64;   // 8 stages
    for (int s = 0; s < NS; s++) {
        if (s < NS - 1) {
            load_chunk((s + 1) & 1, (s + 1) * 64);
            CP_COMMIT();
            CP_WAIT1();
        } else {
            CP_WAIT0();
        }
        __syncthreads();
        const int cur = s & 1;

        #pragma unroll
        for (int kk = 0; kk < 4; kk++) {
            uint32_t af[4][4], bq[4][4];
            #pragma unroll
            for (int mt = 0; mt < 4; mt++) {
                uint32_t addr = sbase + SM_A(cur) + aOff[mt]
                              + (((((uint32_t)kk << 1) | aHi) ^ aRs[mt]) << 4);
                LDSM4(af[mt][0], af[mt][1], af[mt][2], af[mt][3], addr);
            }
            #pragma unroll
            for (int pr = 0; pr < 4; pr++) {
                uint32_t addr = sbase + SM_B(cur) + bOff[pr]
                              + (((((uint32_t)kk << 1) | bHi) ^ bRs[pr]) << 4);
                LDSM4(bq[pr][0], bq[pr][1], bq[pr][2], bq[pr][3], addr);
            }
            #pragma unroll
            for (int mt = 0; mt < 4; mt++)
                #pragma unroll
                for (int pr = 0; pr < 4; pr++) {
                    mma_bf16(acc[mt][pr * 2],     af[mt], &bq[pr][0]);
                    mma_bf16(acc[mt][pr * 2 + 1], af[mt], &bq[pr][2]);
                }
        }
        __syncthreads();
    }

    // epilogue: bias+hidden, tanh, dot V, reduce over n
    float pa[4], pb[4];
    #pragma unroll
    for (int mt = 0; mt < 4; mt++) { pa[mt] = 0.f; pb[mt] = 0.f; }
    #pragma unroll
    for (int nt = 0; nt < 8; nt++) {
        int nn = warpN * 64 + nt * 8 + 2 * tig;
        float s0 = sbias[nn], s1 = sbias[nn + 1];
        float v0 = sV[nn],    v1 = sV[nn + 1];
        #pragma unroll
        for (int mt = 0; mt < 4; mt++) {
            pa[mt] += v0 * tanh_fast(acc[mt][nt][0] + s0) + v1 * tanh_fast(acc[mt][nt][1] + s1);
            pb[mt] += v0 * tanh_fast(acc[mt][nt][2] + s0) + v1 * tanh_fast(acc[mt][nt][3] + s1);
        }
    }
    #pragma unroll
    for (int mt = 0; mt < 4; mt++) {
        pa[mt] += __shfl_xor_sync(0xffffffffu, pa[mt], 1);
        pa[mt] += __shfl_xor_sync(0xffffffffu, pa[mt], 2);
        pb[mt] += __shfl_xor_sync(0xffffffffu, pb[mt], 1);
        pb[mt] += __shfl_xor_sync(0xffffffffu, pb[mt], 2);
    }
    if (tig == 0) {
        #pragma unroll
        for (int mt = 0; mt < 4; mt++) {
            int r = warpM * 64 + mt * 16 + g;
            red[warpN * 128 + r]     = pa[mt];
            red[warpN * 128 + r + 8] = pb[mt];
        }
    }
    __syncthreads();
    if (tid < 128) {
        float s = red[tid] + red[128 + tid] + red[256 + tid] + red[384 + tid];
        g_scoreP[((size_t)b * 2 + blockIdx.y) * TT + t0 + tid] = s;
    }
}

// =====================================================================
// K3: softmax over T per batch
// =====================================================================
__global__ void softmax_kernel() {
    int b = blockIdx.x, tid = threadIdx.x;
    __shared__ float red[256];
    float sv[8];
    float mx = -1e30f;
    #pragma unroll
    for (int i = 0; i < 8; i++) {
        int t = tid + i * 256;
        sv[i] = g_scoreP[(size_t)b * 2 * TT + t] + g_scoreP[((size_t)b * 2 + 1) * TT + t];
        mx = fmaxf(mx, sv[i]);
    }
    red[tid] = mx; __syncthreads();
    for (int o = 128; o > 0; o >>= 1) {
        if (tid < o) red[tid] = fmaxf(red[tid], red[tid + o]);
        __syncthreads();
    }
    mx = red[0]; __syncthreads();
    float sum = 0.f;
    #pragma unroll
    for (int i = 0; i < 8; i++) { sv[i] = expf(sv[i] - mx); sum += sv[i]; }
    red[tid] = sum; __syncthreads();
    for (int o = 128; o > 0; o >>= 1) {
        if (tid < o) red[tid] += red[tid + o];
        __syncthreads();
    }
    float inv = 1.f / red[0];
    #pragma unroll
    for (int i = 0; i < 8; i++) g_w[b * TT + tid + i * 256] = sv[i] * inv;
}

// =====================================================================
// K4: context partials (bf16x2 vectorized)
// =====================================================================
__global__ void context_kernel() {
    int b = blockIdx.y, ch = blockIdx.x, tid = threadIdx.x;   // 256 threads
    const int TC = TT / TCH;
    __shared__ float ws[TC];
    int tBeg = ch * TC;
    for (int i = tid; i < TC; i += 256) ws[i] = g_w[b * TT + tBeg + i];
    __syncthreads();
    float ax = 0.f, ay = 0.f;
    const __nv_bfloat162* Hb =
        (const __nv_bfloat162*)(g_Hb + ((size_t)b * TT + tBeg) * ENC) + tid;
    #pragma unroll 4
    for (int t = 0; t < TC; t++) {
        float2 v = __bfloat1622float2(Hb[(size_t)t * (ENC / 2)]);
        ax += ws[t] * v.x;
        ay += ws[t] * v.y;
    }
    float* dst = g_ctxP + ((size_t)b * TCH + ch) * ENC + 2 * tid;
    dst[0] = ax; dst[1] = ay;
}

// =====================================================================
// K5: GRU combine (Keras reset_after=True, gate order z,r,h)
// =====================================================================
__global__ void gru_combine_kernel(const float* __restrict__ s0,
                                   const float* __restrict__ bi,
                                   const float* __restrict__ br,
                                   float* __restrict__ s_out) {
    int b = blockIdx.x, u = threadIdx.x;
    float xz = bi[u], xr = bi[UNITS + u], xh = bi[2 * UNITS + u];
    float hz = br[u], hr = br[UNITS + u], hh = br[2 * UNITS + u];
    #pragma unroll
    for (int p = 0; p < 8; p++) {
        const float* X  = g_gxP + ((size_t)p * BATCH + b) * (3 * UNITS);
        const float* Hg = g_ghP + ((size_t)p * BATCH + b) * (3 * UNITS);
        xz += X[u];  xr += X[UNITS + u];  xh += X[2 * UNITS + u];
        hz += Hg[u]; hr += Hg[UNITS + u]; hh += Hg[2 * UNITS + u];
    }
    float hprev = s0[b * UNITS + u];
    float z  = 1.f / (1.f + expf(-(xz + hz)));
    float r  = 1.f / (1.f + expf(-(xr + hr)));
    float hc = tanhf(xh + r * hh);
    s_out[b * UNITS + u] = z * hprev + (1.f - z) * hc;
}

// =====================================================================
// K6: gated fusion + vocab projection
// =====================================================================
__global__ void fusion_kernel(const float* __restrict__ Wfa, const float* __restrict__ Wfab,
                              const float* __restrict__ Wff, const float* __restrict__ Wffb,
                              const float* __restrict__ Wfh, const float* __restrict__ Wfhb,
                              const float* __restrict__ Wy,  const float* __restrict__ Wyb,
                              const float* __restrict__ s_t, float* __restrict__ y_out) {
    __shared__ float ctx[ENC], pc[UNITS], st[UNITS], ft[UNITS], yred[512];
    int b = blockIdx.x, u = threadIdx.x;

    float c = 0.f;
    #pragma unroll
    for (int ch = 0; ch < TCH; ch++) c += g_ctxP[((size_t)b * TCH + ch) * ENC + u];
    ctx[u] = c;
    st[u]  = s_t[b * UNITS + u];
    __syncthreads();

    float p = Wfab[u];
    #pragma unroll 4
    for (int k = 0; k < ENC; k++) p += ctx[k] * Wfa[(size_t)k * UNITS + u];
    pc[u] = p;
    __syncthreads();

    float fw = Wffb[u] + Wfhb[u];
    #pragma unroll 4
    for (int k = 0; k < UNITS; k++)
        fw += pc[k] * Wff[(size_t)k * UNITS + u] + st[k] * Wfh[(size_t)k * UNITS + u];
    fw = 1.f / (1.f + expf(-fw));
    ft[u] = pc[u] * fw + st[u];
    __syncthreads();

    int v = u & 31, part = u >> 5;
    float acc = 0.f;
    for (int k = part; k < UNITS; k += 16) acc += ft[k] * Wy[(size_t)k * VOCAB + v];
    yred[u] = acc;
    __syncthreads();
    if (part == 0) {
        float s = Wyb[v];
        #pragma unroll
        for (int pp = 0; pp < 16; pp++) s += yred[pp * 32 + v];
        y_out[b * VOCAB + v] = s;
    }
}

// =====================================================================
extern "C" void kernel_launch(void* const* d_in, const int* in_sizes, int n_in,
                              void* d_out, int out_size) {
    const float* h_t   = (const float*)d_in[0];
    const float* s_t_m = (const float*)d_in[1];
    const float* H     = (const float*)d_in[2];
    const float* s0    = (const float*)d_in[3];
    const float* W1w   = (const float*)d_in[4];
    const float* W1b   = (const float*)d_in[5];
    const float* W2w   = (const float*)d_in[6];
    const float* W2b   = (const float*)d_in[7];
    const float* Vw    = (const float*)d_in[8];
    // d_in[9] = V_b: constant over t, cancels in softmax
    const float* gWx   = (const float*)d_in[10];
    const float* gWh   = (const float*)d_in[11];
    const float* gbi   = (const float*)d_in[12];
    const float* gbr   = (const float*)d_in[13];
    const float* Wfa   = (const float*)d_in[14];
    const float* Wfab  = (const float*)d_in[15];
    const float* Wff   = (const float*)d_in[16];
    const float* Wffb  = (const float*)d_in[17];
    const float* Wfh   = (const float*)d_in[18];
    const float* Wfhb  = (const float*)d_in[19];
    const float* Wy    = (const float*)d_in[20];
    const float* Wyb   = (const float*)d_in[21];

    float* out   = (float*)d_out;
    float* y_out = out;                       // y_t: [64, 32]
    float* s_out = out + BATCH * VOCAB;       // s_t: [64, 512]

    float* d_gx  = nullptr; cudaGetSymbolAddress((void**)&d_gx,  g_gxP);
    float* d_gh  = nullptr; cudaGetSymbolAddress((void**)&d_gh,  g_ghP);
    float* d_hid = nullptr; cudaGetSymbolAddress((void**)&d_hid, g_hidP);

    cudaFuncSetAttribute(score_kernel,
                         cudaFuncAttributeMaxDynamicSharedMemorySize, SMEM_SCORE_BYTES);

    convH_kernel<<<32768, 256>>>(H);
    convW1_kernel<<<dim3(16, 16), dim3(32, 32)>>>(W1w);
    gemm64_kernel<<<dim3(4, 8), 256>>>(s_t_m, W2w, UNITS, d_hid);
    hidden_combine_kernel<<<BATCH, UNITS>>>(W2b);
    gemm64_kernel<<<dim3(12, 8), 256>>>(h_t, gWx, 3 * UNITS, d_gx);
    gemm64_kernel<<<dim3(12, 8), 256>>>(s0, gWh, 3 * UNITS, d_gh);
    score_kernel<<<dim3(TT / 128, 2, BATCH), 256, SMEM_SCORE_BYTES>>>(W1b, Vw);
    gru_combine_kernel<<<BATCH, UNITS>>>(s0, gbi, gbr, s_out);
    softmax_kernel<<<BATCH, 256>>>();
    context_kernel<<<dim3(TCH, BATCH), 256>>>();
    fusion_kernel<<<BATCH, UNITS>>>(Wfa, Wfab, Wff, Wffb, Wfh, Wfhb, Wy, Wyb,
                                    s_out, y_out);
}